// round 1
// baseline (speedup 1.0000x reference)
#include <cuda_runtime.h>
#include <math.h>
#include <stdint.h>

// Problem constants
#define NTOK 4096            // B*T
#define DMODEL 1024
#define NH 16
#define HDIM 64
#define TSEQ 1024
#define GW 32                // grid width/height (32x32)

// ---------------- scratch (device globals; no allocation allowed) ----------------
__device__ float g_qkv[(size_t)NTOK * 3 * DMODEL];     // 50 MB (reused per direction)
__device__ float g_attn[(size_t)NTOK * DMODEL];        // 16 MB (reused per direction)
__device__ float g_concat[(size_t)NTOK * 4 * DMODEL];  // 64 MB
__device__ float g_gated[(size_t)NTOK * 4 * DMODEL];   // 64 MB
__device__ float g_fused[(size_t)NTOK * DMODEL];       // 16 MB

// =================================================================================
// SGEMM: C[m][c_off+n] = sum_k A[m][k] * W[n][k]   (A: MxK row-major, W: NxK row-major)
// mode 0: plain store
// mode 1: C = sigmoid(acc + bias[n]) * aux[m*ldc + n]   (gate epilogue)
// Requires: M%128==0, N%128==0, K%8==0
// =================================================================================
__global__ __launch_bounds__(256) void sgemm_nt(
    const float* __restrict__ A, const float* __restrict__ W,
    float* __restrict__ C, const float* __restrict__ bias,
    const float* __restrict__ aux,
    int M, int N, int K, int ldc, int c_off, int mode)
{
    __shared__ float As[8][128];
    __shared__ float Ws[8][128];
    const int bm = blockIdx.y * 128;
    const int bn = blockIdx.x * 128;
    const int tid = threadIdx.x;
    const int lrow = tid >> 1;          // 0..127
    const int lcol = (tid & 1) * 4;     // 0 or 4
    const int rm = (tid >> 4) * 8;      // row base within tile
    const int cn = (tid & 15) * 8;      // col base within tile

    const float* Aptr = A + (size_t)(bm + lrow) * K + lcol;
    const float* Wptr = W + (size_t)(bn + lrow) * K + lcol;

    float acc[8][8];
#pragma unroll
    for (int i = 0; i < 8; i++)
#pragma unroll
        for (int j = 0; j < 8; j++) acc[i][j] = 0.f;

    for (int k0 = 0; k0 < K; k0 += 8) {
        float4 av = *(const float4*)(Aptr + k0);
        float4 wv = *(const float4*)(Wptr + k0);
        As[lcol + 0][lrow] = av.x; As[lcol + 1][lrow] = av.y;
        As[lcol + 2][lrow] = av.z; As[lcol + 3][lrow] = av.w;
        Ws[lcol + 0][lrow] = wv.x; Ws[lcol + 1][lrow] = wv.y;
        Ws[lcol + 2][lrow] = wv.z; Ws[lcol + 3][lrow] = wv.w;
        __syncthreads();
#pragma unroll
        for (int k = 0; k < 8; k++) {
            float a[8], b[8];
            *(float4*)&a[0] = *(const float4*)&As[k][rm];
            *(float4*)&a[4] = *(const float4*)&As[k][rm + 4];
            *(float4*)&b[0] = *(const float4*)&Ws[k][cn];
            *(float4*)&b[4] = *(const float4*)&Ws[k][cn + 4];
#pragma unroll
            for (int i = 0; i < 8; i++)
#pragma unroll
                for (int j = 0; j < 8; j++) acc[i][j] += a[i] * b[j];
        }
        __syncthreads();
    }

#pragma unroll
    for (int i = 0; i < 8; i++) {
        int m = bm + rm + i;
        float* crow = C + (size_t)m * ldc + c_off + bn;
        if (mode == 1) {
#pragma unroll
            for (int j = 0; j < 8; j++) {
                int n = bn + cn + j;
                float g = 1.f / (1.f + __expf(-(acc[i][j] + bias[n])));
                acc[i][j] = g * aux[(size_t)m * ldc + n];
            }
        }
        *(float4*)(crow + cn)     = *(float4*)&acc[i][0];
        *(float4*)(crow + cn + 4) = *(float4*)&acc[i][4];
    }
}

// =================================================================================
// Flash attention, one direction.
//   qkv: [NTOK][3072] rows token-major (q at h*64+d, k at 1024+..., v at 2048+...)
//   out: [NTOK][1024]
//   tr:  0 = identity token order, 1 = transposed (column-major) order
//   rev: 0 = causal in (permuted) sequence order, 1 = anti-causal
// grid: (16 q-tiles, B*NH). 256 threads. Each thread: 4 q-rows x 4 cols microtile.
// =================================================================================
#define ALD 65
#define ATTN_SMEM (4 * 64 * ALD * 4)

__global__ __launch_bounds__(256) void attn_kernel(
    const float* __restrict__ qkv, float* __restrict__ out, int tr, int rev)
{
    extern __shared__ float sm[];
    float* Qs = sm;                  // [64][ALD]
    float* Ks = Qs + 64 * ALD;
    float* Vs = Ks + 64 * ALD;
    float* Ps = Vs + 64 * ALD;

    const int qt = blockIdx.x;
    const int b  = blockIdx.y >> 4;
    const int h  = blockIdx.y & 15;
    const int tid = threadIdx.x;
    const int qg = (tid >> 4) * 4;   // q row base
    const int kg = (tid & 15) * 4;   // k col base (== d col base for O)
    const size_t base_bq = (size_t)b * TSEQ;

    // Load Q tile (permuted gather)
    for (int idx = tid; idx < 64 * 64; idx += 256) {
        int r = idx >> 6, d = idx & 63;
        int t = qt * 64 + r;
        int tok = tr ? ((t & 31) * 32 + (t >> 5)) : t;
        Qs[r * ALD + d] = qkv[(base_bq + tok) * 3072 + h * 64 + d];
    }

    float m0[4], l0[4], o[4][4];
#pragma unroll
    for (int i = 0; i < 4; i++) {
        m0[i] = -3.4e38f; l0[i] = 0.f;
#pragma unroll
        for (int j = 0; j < 4; j++) o[i][j] = 0.f;
    }

    const int kt_lo = rev ? qt : 0;
    const int kt_hi = rev ? 15 : qt;

    for (int kt = kt_lo; kt <= kt_hi; kt++) {
        __syncthreads();   // prev PV reads done before overwriting K/V
        for (int idx = tid; idx < 64 * 64; idx += 256) {
            int r = idx >> 6, d = idx & 63;
            int t = kt * 64 + r;
            int tok = tr ? ((t & 31) * 32 + (t >> 5)) : t;
            const float* p = qkv + (base_bq + tok) * 3072 + 1024 + h * 64 + d;
            Ks[r * ALD + d] = p[0];
            Vs[r * ALD + d] = p[1024];
        }
        __syncthreads();

        // S = Q K^T
        float s[4][4];
#pragma unroll
        for (int i = 0; i < 4; i++)
#pragma unroll
            for (int j = 0; j < 4; j++) s[i][j] = 0.f;
#pragma unroll 4
        for (int d = 0; d < 64; d++) {
            float qv[4], kv[4];
#pragma unroll
            for (int i = 0; i < 4; i++) qv[i] = Qs[(qg + i) * ALD + d];
#pragma unroll
            for (int j = 0; j < 4; j++) kv[j] = Ks[(kg + j) * ALD + d];
#pragma unroll
            for (int i = 0; i < 4; i++)
#pragma unroll
                for (int j = 0; j < 4; j++) s[i][j] += qv[i] * kv[j];
        }

        // scale, mask (diagonal tile only), online softmax
        float mnew[4];
#pragma unroll
        for (int i = 0; i < 4; i++) {
            float rmax = -3.4e38f;
#pragma unroll
            for (int j = 0; j < 4; j++) {
                float v = s[i][j] * 0.125f;
                if (qt == kt) {
                    bool valid = rev ? (kg + j >= qg + i) : (kg + j <= qg + i);
                    if (!valid) v = -3.4e38f;
                }
                s[i][j] = v;
                rmax = fmaxf(rmax, v);
            }
#pragma unroll
            for (int off = 8; off >= 1; off >>= 1)
                rmax = fmaxf(rmax, __shfl_xor_sync(0xffffffffu, rmax, off));
            mnew[i] = fmaxf(m0[i], rmax);
        }
#pragma unroll
        for (int i = 0; i < 4; i++) {
            float fac = __expf(m0[i] - mnew[i]);
            float rs = 0.f;
#pragma unroll
            for (int j = 0; j < 4; j++) {
                float p = __expf(s[i][j] - mnew[i]);
                Ps[(qg + i) * ALD + kg + j] = p;
                rs += p;
            }
#pragma unroll
            for (int off = 8; off >= 1; off >>= 1)
                rs += __shfl_xor_sync(0xffffffffu, rs, off);
            l0[i] = l0[i] * fac + rs;
            m0[i] = mnew[i];
#pragma unroll
            for (int j = 0; j < 4; j++) o[i][j] *= fac;
        }
        __syncthreads();

        // O += P V
#pragma unroll 4
        for (int k = 0; k < 64; k++) {
            float pv[4], vv[4];
#pragma unroll
            for (int i = 0; i < 4; i++) pv[i] = Ps[(qg + i) * ALD + k];
#pragma unroll
            for (int j = 0; j < 4; j++) vv[j] = Vs[k * ALD + kg + j];
#pragma unroll
            for (int i = 0; i < 4; i++)
#pragma unroll
                for (int j = 0; j < 4; j++) o[i][j] += pv[i] * vv[j];
        }
    }

    // normalize + permuted scatter
#pragma unroll
    for (int i = 0; i < 4; i++) {
        float inv = 1.f / l0[i];
        int t = qt * 64 + qg + i;
        int tok = tr ? ((t & 31) * 32 + (t >> 5)) : t;
        float4 v = make_float4(o[i][0] * inv, o[i][1] * inv, o[i][2] * inv, o[i][3] * inv);
        *(float4*)(out + (base_bq + tok) * 1024 + h * 64 + kg) = v;
    }
}

// =================================================================================
// RMSNorm epilogue: out = rmsnorm(fused + x) * w
// =================================================================================
__global__ __launch_bounds__(256) void rmsnorm_kernel(
    const float* __restrict__ fused, const float* __restrict__ x,
    const float* __restrict__ w, float* __restrict__ out)
{
    const int t = blockIdx.x;
    const int tid = threadIdx.x;
    const float* fr = fused + (size_t)t * 1024;
    const float* xr = x + (size_t)t * 1024;
    float y[4];
    float ss = 0.f;
#pragma unroll
    for (int i = 0; i < 4; i++) {
        int c = tid + i * 256;
        y[i] = fr[c] + xr[c];
        ss += y[i] * y[i];
    }
#pragma unroll
    for (int off = 16; off >= 1; off >>= 1)
        ss += __shfl_xor_sync(0xffffffffu, ss, off);
    __shared__ float red[8];
    if ((tid & 31) == 0) red[tid >> 5] = ss;
    __syncthreads();
    float tot = red[0] + red[1] + red[2] + red[3] + red[4] + red[5] + red[6] + red[7];
    float r = rsqrtf(tot * (1.f / 1024.f) + 1e-6f);
    float* orow = out + (size_t)t * 1024;
#pragma unroll
    for (int i = 0; i < 4; i++) {
        int c = tid + i * 256;
        orow[c] = y[i] * r * w[c];
    }
}

// =================================================================================
// Launch
// =================================================================================
extern "C" void kernel_launch(void* const* d_in, const int* in_sizes, int n_in,
                              void* d_out, int out_size)
{
    const float* x       = (const float*)d_in[0];
    const float* w_qkv[4] = { (const float*)d_in[1], (const float*)d_in[3],
                              (const float*)d_in[5], (const float*)d_in[7] };
    const float* w_o[4]   = { (const float*)d_in[2], (const float*)d_in[4],
                              (const float*)d_in[6], (const float*)d_in[8] };
    const float* w_gate  = (const float*)d_in[9];
    const float* b_gate  = (const float*)d_in[10];
    const float* w_out   = (const float*)d_in[11];
    const float* norm_w  = (const float*)d_in[12];
    float* out = (float*)d_out;

    float *qkv, *attn, *concat, *gated, *fused;
    cudaGetSymbolAddress((void**)&qkv,    g_qkv);
    cudaGetSymbolAddress((void**)&attn,   g_attn);
    cudaGetSymbolAddress((void**)&concat, g_concat);
    cudaGetSymbolAddress((void**)&gated,  g_gated);
    cudaGetSymbolAddress((void**)&fused,  g_fused);

    cudaFuncSetAttribute(attn_kernel, cudaFuncAttributeMaxDynamicSharedMemorySize, ATTN_SMEM);

    for (int dir = 0; dir < 4; dir++) {
        const int tr  = (dir >= 2) ? 1 : 0;   // td/bu: transposed token order
        const int rev = (dir & 1);            // rl/bu: anti-causal

        // QKV projection: [4096,1024] x [3072,1024]^T -> g_qkv [4096,3072]
        sgemm_nt<<<dim3(3072 / 128, 4096 / 128), 256>>>(
            x, w_qkv[dir], qkv, nullptr, nullptr, NTOK, 3072, 1024, 3072, 0, 0);

        // Flash attention -> g_attn [4096,1024]
        attn_kernel<<<dim3(16, 4 * NH), 256, ATTN_SMEM>>>(qkv, attn, tr, rev);

        // Output projection into concat column block dir*1024
        sgemm_nt<<<dim3(1024 / 128, 4096 / 128), 256>>>(
            attn, w_o[dir], concat, nullptr, nullptr, NTOK, 1024, 1024, 4096, dir * 1024, 0);
    }

    // gate = sigmoid(concat @ w_gate^T + b); gated = gate * concat
    sgemm_nt<<<dim3(4096 / 128, 4096 / 128), 256>>>(
        concat, w_gate, gated, b_gate, concat, NTOK, 4096, 4096, 4096, 0, 1);

    // fused = gated @ w_out^T  [4096,1024]
    sgemm_nt<<<dim3(1024 / 128, 4096 / 128), 256>>>(
        gated, w_out, fused, nullptr, nullptr, NTOK, 1024, 4096, 1024, 0, 0);

    // out = rmsnorm(fused + x) * norm_w
    rmsnorm_kernel<<<NTOK, 256>>>(fused, x, norm_w, out);
}

// round 3
// speedup vs baseline: 2.4388x; 2.4388x over previous
#include <cuda_runtime.h>
#include <cuda_bf16.h>
#include <math.h>
#include <stdint.h>

// Problem constants
#define NTOK 4096
#define DMODEL 1024
#define NH 16
#define TSEQ 1024

// ---------------- helpers ----------------
__device__ __forceinline__ uint32_t smem_u32(const void* p) {
    uint32_t a;
    asm("{ .reg .u64 t; cvta.to.shared.u64 t, %1; cvt.u32.u64 %0, t; }" : "=r"(a) : "l"(p));
    return a;
}

#define LDSM4(r, addr) \
    asm volatile("ldmatrix.sync.aligned.m8n8.x4.shared.b16 {%0,%1,%2,%3}, [%4];" \
        : "=r"((r)[0]), "=r"((r)[1]), "=r"((r)[2]), "=r"((r)[3]) : "r"(addr))

#define MMA(c, a, b) \
    asm volatile("mma.sync.aligned.m16n8k16.row.col.f32.bf16.bf16.f32 " \
        "{%0,%1,%2,%3}, {%4,%5,%6,%7}, {%8,%9}, {%0,%1,%2,%3};" \
        : "+f"((c)[0]), "+f"((c)[1]), "+f"((c)[2]), "+f"((c)[3]) \
        : "r"((a)[0]), "r"((a)[1]), "r"((a)[2]), "r"((a)[3]), "r"((b)[0]), "r"((b)[1]))

#define CP_ASYNC16(dst, src) \
    asm volatile("cp.async.cg.shared.global [%0], [%1], 16;" :: "r"(dst), "l"(src) : "memory")
#define CP_COMMIT() asm volatile("cp.async.commit_group;" ::: "memory")
#define CP_WAIT1()  asm volatile("cp.async.wait_group 1;" ::: "memory")
#define CP_WAIT0()  asm volatile("cp.async.wait_group 0;" ::: "memory")

// ---------------- scratch (device globals) ----------------
__device__ __align__(256) __nv_bfloat16 g_xh[(size_t)NTOK * DMODEL];
__device__ __align__(256) __nv_bfloat16 g_xl[(size_t)NTOK * DMODEL];
__device__ __align__(256) __nv_bfloat16 g_wqkvh[(size_t)4 * 3072 * 1024];
__device__ __align__(256) __nv_bfloat16 g_wqkvl[(size_t)4 * 3072 * 1024];
__device__ __align__(256) __nv_bfloat16 g_woh[(size_t)4 * 1024 * 1024];
__device__ __align__(256) __nv_bfloat16 g_wol[(size_t)4 * 1024 * 1024];
__device__ __align__(256) __nv_bfloat16 g_wgh[(size_t)4096 * 4096];
__device__ __align__(256) __nv_bfloat16 g_wgl[(size_t)4096 * 4096];
__device__ __align__(256) __nv_bfloat16 g_wouth[(size_t)1024 * 4096];
__device__ __align__(256) __nv_bfloat16 g_woutl[(size_t)1024 * 4096];
__device__ __align__(256) float g_qkv[(size_t)NTOK * 3072];
__device__ __align__(256) float g_attn[(size_t)NTOK * 1024];
__device__ __align__(256) __nv_bfloat16 g_attnh[(size_t)NTOK * 1024];
__device__ __align__(256) __nv_bfloat16 g_attnl[(size_t)NTOK * 1024];
__device__ __align__(256) __nv_bfloat16 g_conch[(size_t)NTOK * 4096];
__device__ __align__(256) __nv_bfloat16 g_concl[(size_t)NTOK * 4096];
__device__ __align__(256) __nv_bfloat16 g_gath[(size_t)NTOK * 4096];
__device__ __align__(256) __nv_bfloat16 g_gatl[(size_t)NTOK * 4096];
__device__ __align__(256) float g_fused[(size_t)NTOK * 1024];

// ---------------- fp32 -> bf16 hi/lo split ----------------
__global__ __launch_bounds__(256) void convert_split(
    const float* __restrict__ in, __nv_bfloat16* __restrict__ h,
    __nv_bfloat16* __restrict__ l, int n)
{
    for (int i = blockIdx.x * 256 + threadIdx.x; i < n; i += gridDim.x * 256) {
        float v = in[i];
        __nv_bfloat16 hh = __float2bfloat16(v);
        h[i] = hh;
        l[i] = __float2bfloat16(v - __bfloat162float(hh));
    }
}

// =================================================================================
// HMMA bf16 3-term split GEMM: C[m][coff+n] = sum_k A[m][k]*B[n][k]
// A: M x K row-major (hi/lo), B: N x K row-major (hi/lo). CTA 128x128, K-step 32,
// cp.async double buffer, ldmatrix + mma.sync m16n8k16.
// mode 0: Cf = acc (fp32)
// mode 1: (Ch,Cl) = split(acc)
// mode 2: g = sigmoid(acc + bias[n]); (Ch,Cl) = split(g * (Xh+Xl)[m][n])
// Per-stage smem: 4 tiles (Ah,Al,Bh,Bl) of 128 rows x 64B, swizzled.
// =================================================================================
#define STAGEB 32768
#define GSMEM  (2 * STAGEB)

__device__ __forceinline__ void load_stage(
    const __nv_bfloat16* __restrict__ Ah, const __nv_bfloat16* __restrict__ Al,
    const __nv_bfloat16* __restrict__ Bh, const __nv_bfloat16* __restrict__ Bl,
    int K, int k0, int bm, int bn, uint32_t sstage, int tid)
{
#pragma unroll
    for (int it = 0; it < 8; it++) {
        int cidx = tid + it * 256;
        int t = cidx >> 9;
        int row = (cidx >> 2) & 127;
        int c = cidx & 3;
        const __nv_bfloat16* src = (t == 0) ? Ah : (t == 1) ? Al : (t == 2) ? Bh : Bl;
        int rb = (t < 2) ? bm : bn;
        const __nv_bfloat16* gsrc = src + (size_t)(rb + row) * K + k0 + c * 8;
        uint32_t dst = sstage + t * 8192 + row * 64 + ((c ^ ((row >> 1) & 3)) << 4);
        CP_ASYNC16(dst, gsrc);
    }
    CP_COMMIT();
}

__global__ __launch_bounds__(256) void gemm_bf16(
    const __nv_bfloat16* __restrict__ Ah, const __nv_bfloat16* __restrict__ Al,
    const __nv_bfloat16* __restrict__ Bh, const __nv_bfloat16* __restrict__ Bl,
    int K, int mode,
    float* __restrict__ Cf,
    __nv_bfloat16* __restrict__ Ch, __nv_bfloat16* __restrict__ Cl,
    const float* __restrict__ bias,
    const __nv_bfloat16* __restrict__ Xh, const __nv_bfloat16* __restrict__ Xl,
    int ldc, int coff)
{
    extern __shared__ char smem[];
    const uint32_t sb = smem_u32(smem);
    const int tid = threadIdx.x;
    const int wid = tid >> 5, lane = tid & 31;
    const int bm = blockIdx.y * 128;
    const int bn = blockIdx.x * 128;
    const int wm = (wid >> 2) * 64;   // warp m offset in CTA tile
    const int wn = (wid & 3) * 32;    // warp n offset

    float acc[4][4][4];
#pragma unroll
    for (int mi = 0; mi < 4; mi++)
#pragma unroll
        for (int nj = 0; nj < 4; nj++)
#pragma unroll
            for (int q = 0; q < 4; q++) acc[mi][nj][q] = 0.f;

    const int nchunk = K >> 5;
    load_stage(Ah, Al, Bh, Bl, K, 0, bm, bn, sb, tid);

    for (int i = 0; i < nchunk; i++) {
        if (i + 1 < nchunk) {
            load_stage(Ah, Al, Bh, Bl, K, (i + 1) << 5, bm, bn,
                       sb + ((i + 1) & 1) * STAGEB, tid);
            CP_WAIT1();
        } else {
            CP_WAIT0();
        }
        __syncthreads();

        const uint32_t st = sb + (i & 1) * STAGEB;
#pragma unroll
        for (int ks = 0; ks < 2; ks++) {
            uint32_t ah[4][4], al[4][4], bh[2][4], bl[2][4];
#pragma unroll
            for (int mi = 0; mi < 4; mi++) {
                int row = wm + mi * 16 + (lane & 7) + (((lane >> 3) & 1) << 3);
                int ch = (lane >> 4) + ks * 2;
                uint32_t ad = st + row * 64 + ((ch ^ ((row >> 1) & 3)) << 4);
                LDSM4(ah[mi], ad);
                LDSM4(al[mi], ad + 8192);
            }
#pragma unroll
            for (int nb = 0; nb < 2; nb++) {
                int row = wn + nb * 16 + (lane & 7) + ((lane >> 4) << 3);
                int ch = ((lane >> 3) & 1) + ks * 2;
                uint32_t ad = st + 16384 + row * 64 + ((ch ^ ((row >> 1) & 3)) << 4);
                LDSM4(bh[nb], ad);
                LDSM4(bl[nb], ad + 8192);
            }
#pragma unroll
            for (int mi = 0; mi < 4; mi++)
#pragma unroll
                for (int nj = 0; nj < 4; nj++) {
                    uint32_t* bhp = &bh[nj >> 1][(nj & 1) * 2];
                    uint32_t* blp = &bl[nj >> 1][(nj & 1) * 2];
                    MMA(acc[mi][nj], ah[mi], bhp);
                    MMA(acc[mi][nj], ah[mi], blp);
                    MMA(acc[mi][nj], al[mi], bhp);
                }
        }
        __syncthreads();
    }

    // epilogue
#pragma unroll
    for (int mi = 0; mi < 4; mi++) {
#pragma unroll
        for (int r = 0; r < 2; r++) {
            int m = bm + wm + mi * 16 + (lane >> 2) + r * 8;
#pragma unroll
            for (int nj = 0; nj < 4; nj++) {
                int n = bn + wn + nj * 8 + (lane & 3) * 2;
                float v0 = acc[mi][nj][r * 2 + 0];
                float v1 = acc[mi][nj][r * 2 + 1];
                size_t o = (size_t)m * ldc + coff + n;
                if (mode == 0) {
                    *(float2*)(Cf + o) = make_float2(v0, v1);
                } else {
                    if (mode == 2) {
                        float g0 = 1.f / (1.f + __expf(-(v0 + bias[n])));
                        float g1 = 1.f / (1.f + __expf(-(v1 + bias[n + 1])));
                        float a0 = __bfloat162float(Xh[o]) + __bfloat162float(Xl[o]);
                        float a1 = __bfloat162float(Xh[o + 1]) + __bfloat162float(Xl[o + 1]);
                        v0 = g0 * a0; v1 = g1 * a1;
                    }
                    __nv_bfloat16 h0 = __float2bfloat16(v0);
                    __nv_bfloat16 h1 = __float2bfloat16(v1);
                    __nv_bfloat16 l0 = __float2bfloat16(v0 - __bfloat162float(h0));
                    __nv_bfloat16 l1 = __float2bfloat16(v1 - __bfloat162float(h1));
                    __nv_bfloat162 hp; hp.x = h0; hp.y = h1;
                    __nv_bfloat162 lp; lp.x = l0; lp.y = l1;
                    *(__nv_bfloat162*)(Ch + o) = hp;
                    *(__nv_bfloat162*)(Cl + o) = lp;
                }
            }
        }
    }
}

// =================================================================================
// Flash attention (fp32, unchanged from R1 passing version)
// =================================================================================
#define ALD 65
#define ATTN_SMEM (4 * 64 * ALD * 4)

__global__ __launch_bounds__(256) void attn_kernel(
    const float* __restrict__ qkv, float* __restrict__ out, int tr, int rev)
{
    extern __shared__ float sm[];
    float* Qs = sm;
    float* Ks = Qs + 64 * ALD;
    float* Vs = Ks + 64 * ALD;
    float* Ps = Vs + 64 * ALD;

    const int qt = blockIdx.x;
    const int b  = blockIdx.y >> 4;
    const int h  = blockIdx.y & 15;
    const int tid = threadIdx.x;
    const int qg = (tid >> 4) * 4;
    const int kg = (tid & 15) * 4;
    const size_t base_bq = (size_t)b * TSEQ;

    for (int idx = tid; idx < 64 * 64; idx += 256) {
        int r = idx >> 6, d = idx & 63;
        int t = qt * 64 + r;
        int tok = tr ? ((t & 31) * 32 + (t >> 5)) : t;
        Qs[r * ALD + d] = qkv[(base_bq + tok) * 3072 + h * 64 + d];
    }

    float m0[4], l0[4], o[4][4];
#pragma unroll
    for (int i = 0; i < 4; i++) {
        m0[i] = -3.4e38f; l0[i] = 0.f;
#pragma unroll
        for (int j = 0; j < 4; j++) o[i][j] = 0.f;
    }

    const int kt_lo = rev ? qt : 0;
    const int kt_hi = rev ? 15 : qt;

    for (int kt = kt_lo; kt <= kt_hi; kt++) {
        __syncthreads();
        for (int idx = tid; idx < 64 * 64; idx += 256) {
            int r = idx >> 6, d = idx & 63;
            int t = kt * 64 + r;
            int tok = tr ? ((t & 31) * 32 + (t >> 5)) : t;
            const float* p = qkv + (base_bq + tok) * 3072 + 1024 + h * 64 + d;
            Ks[r * ALD + d] = p[0];
            Vs[r * ALD + d] = p[1024];
        }
        __syncthreads();

        float s[4][4];
#pragma unroll
        for (int i = 0; i < 4; i++)
#pragma unroll
            for (int j = 0; j < 4; j++) s[i][j] = 0.f;
#pragma unroll 4
        for (int d = 0; d < 64; d++) {
            float qv[4], kv[4];
#pragma unroll
            for (int i = 0; i < 4; i++) qv[i] = Qs[(qg + i) * ALD + d];
#pragma unroll
            for (int j = 0; j < 4; j++) kv[j] = Ks[(kg + j) * ALD + d];
#pragma unroll
            for (int i = 0; i < 4; i++)
#pragma unroll
                for (int j = 0; j < 4; j++) s[i][j] += qv[i] * kv[j];
        }

        float mnew[4];
#pragma unroll
        for (int i = 0; i < 4; i++) {
            float rmax = -3.4e38f;
#pragma unroll
            for (int j = 0; j < 4; j++) {
                float v = s[i][j] * 0.125f;
                if (qt == kt) {
                    bool valid = rev ? (kg + j >= qg + i) : (kg + j <= qg + i);
                    if (!valid) v = -3.4e38f;
                }
                s[i][j] = v;
                rmax = fmaxf(rmax, v);
            }
#pragma unroll
            for (int off = 8; off >= 1; off >>= 1)
                rmax = fmaxf(rmax, __shfl_xor_sync(0xffffffffu, rmax, off));
            mnew[i] = fmaxf(m0[i], rmax);
        }
#pragma unroll
        for (int i = 0; i < 4; i++) {
            float fac = __expf(m0[i] - mnew[i]);
            float rs = 0.f;
#pragma unroll
            for (int j = 0; j < 4; j++) {
                float p = __expf(s[i][j] - mnew[i]);
                Ps[(qg + i) * ALD + kg + j] = p;
                rs += p;
            }
#pragma unroll
            for (int off = 8; off >= 1; off >>= 1)
                rs += __shfl_xor_sync(0xffffffffu, rs, off);
            l0[i] = l0[i] * fac + rs;
            m0[i] = mnew[i];
#pragma unroll
            for (int j = 0; j < 4; j++) o[i][j] *= fac;
        }
        __syncthreads();

#pragma unroll 4
        for (int k = 0; k < 64; k++) {
            float pv[4], vv[4];
#pragma unroll
            for (int i = 0; i < 4; i++) pv[i] = Ps[(qg + i) * ALD + k];
#pragma unroll
            for (int j = 0; j < 4; j++) vv[j] = Vs[k * ALD + kg + j];
#pragma unroll
            for (int i = 0; i < 4; i++)
#pragma unroll
                for (int j = 0; j < 4; j++) o[i][j] += pv[i] * vv[j];
        }
    }

#pragma unroll
    for (int i = 0; i < 4; i++) {
        float inv = 1.f / l0[i];
        int t = qt * 64 + qg + i;
        int tok = tr ? ((t & 31) * 32 + (t >> 5)) : t;
        float4 v = make_float4(o[i][0] * inv, o[i][1] * inv, o[i][2] * inv, o[i][3] * inv);
        *(float4*)(out + (base_bq + tok) * 1024 + h * 64 + kg) = v;
    }
}

// =================================================================================
// RMSNorm epilogue
// =================================================================================
__global__ __launch_bounds__(256) void rmsnorm_kernel(
    const float* __restrict__ fused, const float* __restrict__ x,
    const float* __restrict__ w, float* __restrict__ out)
{
    const int t = blockIdx.x;
    const int tid = threadIdx.x;
    const float* fr = fused + (size_t)t * 1024;
    const float* xr = x + (size_t)t * 1024;
    float y[4];
    float ss = 0.f;
#pragma unroll
    for (int i = 0; i < 4; i++) {
        int c = tid + i * 256;
        y[i] = fr[c] + xr[c];
        ss += y[i] * y[i];
    }
#pragma unroll
    for (int off = 16; off >= 1; off >>= 1)
        ss += __shfl_xor_sync(0xffffffffu, ss, off);
    __shared__ float red[8];
    if ((tid & 31) == 0) red[tid >> 5] = ss;
    __syncthreads();
    float tot = red[0] + red[1] + red[2] + red[3] + red[4] + red[5] + red[6] + red[7];
    float r = rsqrtf(tot * (1.f / 1024.f) + 1e-6f);
    float* orow = out + (size_t)t * 1024;
#pragma unroll
    for (int i = 0; i < 4; i++) {
        int c = tid + i * 256;
        orow[c] = y[i] * r * w[c];
    }
}

// =================================================================================
// Launch
// =================================================================================
extern "C" void kernel_launch(void* const* d_in, const int* in_sizes, int n_in,
                              void* d_out, int out_size)
{
    const float* x       = (const float*)d_in[0];
    const float* w_qkv[4] = { (const float*)d_in[1], (const float*)d_in[3],
                              (const float*)d_in[5], (const float*)d_in[7] };
    const float* w_o[4]   = { (const float*)d_in[2], (const float*)d_in[4],
                              (const float*)d_in[6], (const float*)d_in[8] };
    const float* w_gate  = (const float*)d_in[9];
    const float* b_gate  = (const float*)d_in[10];
    const float* w_out   = (const float*)d_in[11];
    const float* norm_w  = (const float*)d_in[12];
    float* out = (float*)d_out;

    __nv_bfloat16 *xh, *xl, *wqkvh, *wqkvl, *woh, *wol, *wgh, *wgl, *wouth, *woutl;
    __nv_bfloat16 *attnh, *attnl, *conch, *concl, *gath, *gatl;
    float *qkv, *attn, *fused;
    cudaGetSymbolAddress((void**)&xh, g_xh);       cudaGetSymbolAddress((void**)&xl, g_xl);
    cudaGetSymbolAddress((void**)&wqkvh, g_wqkvh); cudaGetSymbolAddress((void**)&wqkvl, g_wqkvl);
    cudaGetSymbolAddress((void**)&woh, g_woh);     cudaGetSymbolAddress((void**)&wol, g_wol);
    cudaGetSymbolAddress((void**)&wgh, g_wgh);     cudaGetSymbolAddress((void**)&wgl, g_wgl);
    cudaGetSymbolAddress((void**)&wouth, g_wouth); cudaGetSymbolAddress((void**)&woutl, g_woutl);
    cudaGetSymbolAddress((void**)&attnh, g_attnh); cudaGetSymbolAddress((void**)&attnl, g_attnl);
    cudaGetSymbolAddress((void**)&conch, g_conch); cudaGetSymbolAddress((void**)&concl, g_concl);
    cudaGetSymbolAddress((void**)&gath, g_gath);   cudaGetSymbolAddress((void**)&gatl, g_gatl);
    cudaGetSymbolAddress((void**)&qkv, g_qkv);
    cudaGetSymbolAddress((void**)&attn, g_attn);
    cudaGetSymbolAddress((void**)&fused, g_fused);

    cudaFuncSetAttribute(attn_kernel, cudaFuncAttributeMaxDynamicSharedMemorySize, ATTN_SMEM);
    cudaFuncSetAttribute(gemm_bf16, cudaFuncAttributeMaxDynamicSharedMemorySize, GSMEM);

    // split conversions
    convert_split<<<2048, 256>>>(x, xh, xl, NTOK * DMODEL);
    for (int d = 0; d < 4; d++) {
        convert_split<<<2048, 256>>>(w_qkv[d], wqkvh + (size_t)d * 3072 * 1024,
                                     wqkvl + (size_t)d * 3072 * 1024, 3072 * 1024);
        convert_split<<<2048, 256>>>(w_o[d], woh + (size_t)d * 1024 * 1024,
                                     wol + (size_t)d * 1024 * 1024, 1024 * 1024);
    }
    convert_split<<<4096, 256>>>(w_gate, wgh, wgl, 4096 * 4096);
    convert_split<<<2048, 256>>>(w_out, wouth, woutl, 1024 * 4096);

    for (int dir = 0; dir < 4; dir++) {
        const int tr  = (dir >= 2) ? 1 : 0;
        const int rev = (dir & 1);

        // QKV: [4096,1024] x [3072,1024]^T -> qkv fp32 [4096,3072]
        gemm_bf16<<<dim3(3072 / 128, 4096 / 128), 256, GSMEM>>>(
            xh, xl, wqkvh + (size_t)dir * 3072 * 1024, wqkvl + (size_t)dir * 3072 * 1024,
            1024, 0, qkv, nullptr, nullptr, nullptr, nullptr, nullptr, 3072, 0);

        attn_kernel<<<dim3(16, 4 * NH), 256, ATTN_SMEM>>>(qkv, attn, tr, rev);
        convert_split<<<2048, 256>>>(attn, attnh, attnl, NTOK * 1024);

        // O-proj -> concat block (bf16 split)
        gemm_bf16<<<dim3(1024 / 128, 4096 / 128), 256, GSMEM>>>(
            attnh, attnl, woh + (size_t)dir * 1024 * 1024, wol + (size_t)dir * 1024 * 1024,
            1024, 1, nullptr, conch, concl, nullptr, nullptr, nullptr, 4096, dir * 1024);
    }

    // gate: sigmoid(concat @ w_gate^T + b) * concat -> gated (bf16 split)
    gemm_bf16<<<dim3(4096 / 128, 4096 / 128), 256, GSMEM>>>(
        conch, concl, wgh, wgl, 4096, 2, nullptr, gath, gatl, b_gate, conch, concl, 4096, 0);

    // out: gated @ w_out^T -> fused fp32
    gemm_bf16<<<dim3(1024 / 128, 4096 / 128), 256, GSMEM>>>(
        gath, gatl, wouth, woutl, 4096, 0, fused, nullptr, nullptr, nullptr, nullptr, nullptr, 1024, 0);

    rmsnorm_kernel<<<NTOK, 256>>>(fused, x, norm_w, out);
}